// round 15
// baseline (speedup 1.0000x reference)
#include <cuda_runtime.h>
#include <cuda_fp16.h>
#include <cstdint>

// VisionDynamicSparseAttention pipeline (round 15 = R14 + .cs streaming hints on score/P traffic):
//  0) split kernels: hidden/qkv_w/proj_w -> fp16 hi+lo pairs
//  1) QKV via compensated fp16 HMMA, cp.async double-buffered (+bias)
//  2) Q@K^T comp-HMMA (R11 pipeline); score stores via st.global.cs (evict-first)
//  3) select: exact fp32 k-th largest (R6, frozen); ld.cs score reads, st.cs P writes
//  4) PV fp16 HMMA, cp.async 2-stage ring -> ctx fp16 hi+lo
//  5) proj via compensated fp16 HMMA, cp.async (+bias) -> d_out fp32

namespace {
constexpr int NH    = 12;
constexpr int HDIM  = 64;
constexpr int BATCH = 2;
constexpr int SEQ   = 2048;
constexpr int HID   = 768;
constexpr int HEADS = BATCH * NH;   // 24
constexpr int KSEL  = 1024;
constexpr float L2E = 1.4426950408889634f;
// hgemm tiling
constexpr int GLDA = 40;                  // halves pitch (80B rows)
constexpr int GTS  = 128 * GLDA;          // halves per tensor tile
constexpr int GSMEM = 2 * 4 * GTS * 2;    // bytes: 2 stages x 4 tensors
// qk tiling (R11)
constexpr int QLDQ = 72;                  // halves pitch (144B rows)
constexpr int QTS  = 128 * QLDQ;          // halves per tile
constexpr int QK_SMEM = 4 * QTS * 2;      // bytes: Qh,Kh,Ql,Kl resident (73728)
// pv tiling (R14)
constexpr int PLDP = 72;                  // halves pitch
constexpr int PTS  = 128 * PLDP;          // P tile halves
constexpr int VTS  = 64 * PLDP;           // V tile halves
constexpr int PSTG = PTS + VTS;           // halves per stage
constexpr int PV_SMEM = 2 * PSTG * 2;     // bytes (55296)
}

// fp16 hi/lo operand copies
__device__ __half g_hidh[BATCH * SEQ * HID];
__device__ __half g_hidl[BATCH * SEQ * HID];
__device__ __half g_wqh[3 * HID * HID];
__device__ __half g_wql[3 * HID * HID];
__device__ __half g_wph[HID * HID];
__device__ __half g_wpl[HID * HID];
// per-head q/k (hi+lo), v
__device__ __half g_qh[HEADS * SEQ * HDIM];
__device__ __half g_ql[HEADS * SEQ * HDIM];
__device__ __half g_kh[HEADS * SEQ * HDIM];
__device__ __half g_kl[HEADS * SEQ * HDIM];
__device__ __half g_vh[HEADS * SEQ * HDIM];
// attention
__device__ float  g_attn[(long long)HEADS * SEQ * SEQ];  // fp32 scores
__device__ __half g_p[(long long)HEADS * SEQ * SEQ];     // fp16 probs
// context (hi+lo for proj A operand)
__device__ __half g_ctxh[BATCH * SEQ * HID];
__device__ __half g_ctxl[BATCH * SEQ * HID];

// FMA-only exp2 (range-reduced deg-5; rel err ~2.4e-6)
__device__ __forceinline__ float fast_exp2(float y) {
  float t = y + 12582912.0f;
  int   i = __float_as_int(t);
  float f = y - (t - 12582912.0f);
  float p = 1.3333558146e-3f;
  p = fmaf(p, f, 9.6181291918e-3f);
  p = fmaf(p, f, 5.5504108665e-2f);
  p = fmaf(p, f, 2.4022650696e-1f);
  p = fmaf(p, f, 6.9314718056e-1f);
  p = fmaf(p, f, 1.0f);
  return __int_as_float(__float_as_int(p) + (i << 23));
}

// ---------------------------------------------------------------------------
// split: fp32 -> fp16 hi + lo residual
// ---------------------------------------------------------------------------
__global__ void __launch_bounds__(256) split_kernel(const float* __restrict__ src,
                                                    __half* __restrict__ hi,
                                                    __half* __restrict__ lo, int n4) {
  int i = blockIdx.x * blockDim.x + threadIdx.x;
  if (i >= n4) return;
  float4 v = ((const float4*)src)[i];
  __half hx = __float2half_rn(v.x), hy = __float2half_rn(v.y);
  __half hz = __float2half_rn(v.z), hw = __float2half_rn(v.w);
  union { __half2 h2[2]; uint2 u; } H, L;
  H.h2[0] = __halves2half2(hx, hy);
  H.h2[1] = __halves2half2(hz, hw);
  L.h2[0] = __floats2half2_rn(v.x - __half2float(hx), v.y - __half2float(hy));
  L.h2[1] = __floats2half2_rn(v.z - __half2float(hz), v.w - __half2float(hw));
  ((uint2*)hi)[i] = H.u;
  ((uint2*)lo)[i] = L.u;
}

// ---------------------------------------------------------------------------
// HMMA / async primitives
// ---------------------------------------------------------------------------
__device__ __forceinline__ void ldsm_x4(uint32_t& r0, uint32_t& r1, uint32_t& r2,
                                        uint32_t& r3, uint32_t saddr) {
  asm volatile("ldmatrix.sync.aligned.m8n8.x4.shared.b16 {%0,%1,%2,%3}, [%4];"
               : "=r"(r0), "=r"(r1), "=r"(r2), "=r"(r3) : "r"(saddr));
}
__device__ __forceinline__ void ldsm_x4_t(uint32_t& r0, uint32_t& r1, uint32_t& r2,
                                          uint32_t& r3, uint32_t saddr) {
  asm volatile("ldmatrix.sync.aligned.m8n8.x4.trans.shared.b16 {%0,%1,%2,%3}, [%4];"
               : "=r"(r0), "=r"(r1), "=r"(r2), "=r"(r3) : "r"(saddr));
}
__device__ __forceinline__ void mma16816(float* c, const uint32_t a[4],
                                         uint32_t b0, uint32_t b1) {
  asm volatile(
      "mma.sync.aligned.m16n8k16.row.col.f32.f16.f16.f32 "
      "{%0,%1,%2,%3}, {%4,%5,%6,%7}, {%8,%9}, {%0,%1,%2,%3};"
      : "+f"(c[0]), "+f"(c[1]), "+f"(c[2]), "+f"(c[3])
      : "r"(a[0]), "r"(a[1]), "r"(a[2]), "r"(a[3]), "r"(b0), "r"(b1));
}
__device__ __forceinline__ void cp_async16(uint32_t saddr, const void* g) {
  asm volatile("cp.async.cg.shared.global [%0], [%1], 16;" :: "r"(saddr), "l"(g));
}

// ---------------------------------------------------------------------------
// Compensated fp16 GEMM, cp.async 2-stage (R8/R10-proven).
// ---------------------------------------------------------------------------
template <int KDIM, class Cfg>
__global__ void __launch_bounds__(256) hgemm_comp(Cfg cfg) {
  constexpr int BK = 32;
  constexpr int NIT = KDIM / BK;
  extern __shared__ __half dynsm[];

  const __half* __restrict__ src[4] = {cfg.Ah(), cfg.Al(), cfg.Bh(), cfg.Bl()};

  const int tid = threadIdx.x;
  const int warp = tid >> 5, lane = tid & 31;
  const int warp_m = warp >> 1, warp_n = warp & 1;
  const int m0 = blockIdx.y * 128;
  const int n0 = blockIdx.x * 128;
  const int row0[4] = {m0, m0, n0, n0};

  const int lr = tid >> 2;
  const int lc = (tid & 3) << 3;

  const uint32_t sm_base = (uint32_t)__cvta_generic_to_shared(dynsm);

  float c[2][8][4];
#pragma unroll
  for (int mi = 0; mi < 2; mi++)
#pragma unroll
    for (int ni = 0; ni < 8; ni++)
#pragma unroll
      for (int j = 0; j < 4; j++) c[mi][ni][j] = 0.f;

  auto issue = [&](int stage, int k0) {
#pragma unroll
    for (int t = 0; t < 4; t++) {
      const uint32_t tbase = sm_base + (uint32_t)(stage * 4 + t) * GTS * 2;
#pragma unroll
      for (int h = 0; h < 2; h++) {
        const int r = lr + 64 * h;
        cp_async16(tbase + (uint32_t)(r * GLDA + lc) * 2,
                   &src[t][(long)(row0[t] + r) * KDIM + k0 + lc]);
      }
    }
  };

  issue(0, 0);
  asm volatile("cp.async.commit_group;" ::: "memory");

  const uint32_t a_off = ((warp_m * 32 + (lane & 15)) * GLDA + ((lane >> 4) << 3)) * 2;
  const uint32_t b_off = ((warp_n * 64 + (lane & 15)) * GLDA + ((lane >> 4) << 3)) * 2;

#pragma unroll 1
  for (int it = 0; it < NIT; it++) {
    if (it + 1 < NIT) {
      issue((it + 1) & 1, (it + 1) * BK);
      asm volatile("cp.async.commit_group;" ::: "memory");
      asm volatile("cp.async.wait_group 1;" ::: "memory");
    } else {
      asm volatile("cp.async.wait_group 0;" ::: "memory");
    }
    __syncthreads();

    const int st = it & 1;
    const uint32_t ah_b = sm_base + (uint32_t)(st * 4 + 0) * GTS * 2;
    const uint32_t al_b = sm_base + (uint32_t)(st * 4 + 1) * GTS * 2;
    const uint32_t bh_b = sm_base + (uint32_t)(st * 4 + 2) * GTS * 2;
    const uint32_t bl_b = sm_base + (uint32_t)(st * 4 + 3) * GTS * 2;

#pragma unroll
    for (int ks = 0; ks < 2; ks++) {
      uint32_t ah[2][4], al[2][4];
#pragma unroll
      for (int mi = 0; mi < 2; mi++) {
        ldsm_x4(ah[mi][0], ah[mi][1], ah[mi][2], ah[mi][3],
                ah_b + a_off + (mi * 16 * GLDA + ks * 16) * 2);
        ldsm_x4(al[mi][0], al[mi][1], al[mi][2], al[mi][3],
                al_b + a_off + (mi * 16 * GLDA + ks * 16) * 2);
      }
#pragma unroll
      for (int nig = 0; nig < 4; nig++) {
        uint32_t bh0, bh1, bh2, bh3, bl0, bl1, bl2, bl3;
        ldsm_x4(bh0, bh1, bh2, bh3, bh_b + b_off + (nig * 16 * GLDA + ks * 16) * 2);
        ldsm_x4(bl0, bl1, bl2, bl3, bl_b + b_off + (nig * 16 * GLDA + ks * 16) * 2);
#pragma unroll
        for (int mi = 0; mi < 2; mi++) {
          mma16816(c[mi][2 * nig + 0], ah[mi], bh0, bh2);
          mma16816(c[mi][2 * nig + 1], ah[mi], bh1, bh3);
          mma16816(c[mi][2 * nig + 0], ah[mi], bl0, bl2);
          mma16816(c[mi][2 * nig + 1], ah[mi], bl1, bl3);
          mma16816(c[mi][2 * nig + 0], al[mi], bh0, bh2);
          mma16816(c[mi][2 * nig + 1], al[mi], bh1, bh3);
        }
      }
    }
    __syncthreads();
  }
  cfg.epi(c, m0, n0, warp_m, warp_n, lane);
}

// ---------------- Stage 1: QKV (comp-HMMA) ----------------
struct CfgQKV3 {
  const float* bias;
  __device__ __forceinline__ const __half* Ah() const { return g_hidh; }
  __device__ __forceinline__ const __half* Al() const { return g_hidl; }
  __device__ __forceinline__ const __half* Bh() const { return g_wqh; }
  __device__ __forceinline__ const __half* Bl() const { return g_wql; }
  __device__ __forceinline__ void handle(int m, int n, float v0, float v1) const {
    const int b = m >> 11, s = m & (SEQ - 1);
    const int sec = n / HID;
    const int rem = n - sec * HID;
    const int h = rem >> 6, d = rem & 63;
    const long base = ((long)((b * NH + h) * SEQ + s)) * HDIM + d;
    v0 += bias[n];
    v1 += bias[n + 1];
    if (sec == 0) { v0 *= 0.125f; v1 *= 0.125f; }
    __half h0 = __float2half_rn(v0), h1 = __float2half_rn(v1);
    __half2 hi = __halves2half2(h0, h1);
    if (sec == 2) {
      *(__half2*)&g_vh[base] = hi;
      return;
    }
    __half2 lo = __floats2half2_rn(v0 - __half2float(h0), v1 - __half2float(h1));
    if (sec == 0) {
      *(__half2*)&g_qh[base] = hi;
      *(__half2*)&g_ql[base] = lo;
    } else {
      *(__half2*)&g_kh[base] = hi;
      *(__half2*)&g_kl[base] = lo;
    }
  }
  __device__ __forceinline__ void epi(const float c[2][8][4], int m0, int n0,
                                      int warp_m, int warp_n, int lane) const {
#pragma unroll
    for (int mi = 0; mi < 2; mi++) {
      const int r = m0 + warp_m * 32 + mi * 16 + (lane >> 2);
#pragma unroll
      for (int ni = 0; ni < 8; ni++) {
        const int n = n0 + warp_n * 64 + ni * 8 + 2 * (lane & 3);
        handle(r, n, c[mi][ni][0], c[mi][ni][1]);
        handle(r + 8, n, c[mi][ni][2], c[mi][ni][3]);
      }
    }
  }
};

// ---------------- Stage 5: proj (comp-HMMA) ----------------
struct CfgProj3 {
  const float* bias;
  float* out;
  __device__ __forceinline__ const __half* Ah() const { return g_ctxh; }
  __device__ __forceinline__ const __half* Al() const { return g_ctxl; }
  __device__ __forceinline__ const __half* Bh() const { return g_wph; }
  __device__ __forceinline__ const __half* Bl() const { return g_wpl; }
  __device__ __forceinline__ void epi(const float c[2][8][4], int m0, int n0,
                                      int warp_m, int warp_n, int lane) const {
#pragma unroll
    for (int mi = 0; mi < 2; mi++) {
      const int r = m0 + warp_m * 32 + mi * 16 + (lane >> 2);
#pragma unroll
      for (int ni = 0; ni < 8; ni++) {
        const int n = n0 + warp_n * 64 + ni * 8 + 2 * (lane & 3);
        const float b0 = bias[n], b1 = bias[n + 1];
        *(float2*)&out[(long)r * HID + n] =
            make_float2(c[mi][ni][0] + b0, c[mi][ni][1] + b1);
        *(float2*)&out[(long)(r + 8) * HID + n] =
            make_float2(c[mi][ni][2] + b0, c[mi][ni][3] + b1);
      }
    }
  }
};

// ---------------------------------------------------------------------------
// Stage 2: compensated QK^T, cp.async pipelined (R11); score stores evict-first.
// ---------------------------------------------------------------------------
__global__ void __launch_bounds__(256) qk_comp_kernel() {
  extern __shared__ __half qsm[];

  const int head = blockIdx.z;
  const int m0 = blockIdx.y * 128;
  const int n0 = blockIdx.x * 128;
  const long qoff = (long)head * SEQ * HDIM;

  const int tid = threadIdx.x;
  const int warp = tid >> 5, lane = tid & 31;
  const int warp_m = warp >> 1, warp_n = warp & 1;

  // tile order: 0=Qh, 1=Kh (group A); 2=Ql, 3=Kl (group B)
  const __half* __restrict__ src[4] = {g_qh + qoff, g_kh + qoff,
                                       g_ql + qoff, g_kl + qoff};
  const int row0[4] = {m0, n0, m0, n0};

  const int lrow = tid >> 1;
  const int lcol = (tid & 1) * 32;
  const uint32_t smb = (uint32_t)__cvta_generic_to_shared(qsm);

#pragma unroll
  for (int t = 0; t < 2; t++) {
    const uint32_t tbase = smb + (uint32_t)t * QTS * 2;
    const __half* g = &src[t][(long)(row0[t] + lrow) * HDIM + lcol];
#pragma unroll
    for (int i = 0; i < 4; i++)
      cp_async16(tbase + (uint32_t)(lrow * QLDQ + lcol + i * 8) * 2, g + i * 8);
  }
  asm volatile("cp.async.commit_group;" ::: "memory");
#pragma unroll
  for (int t = 2; t < 4; t++) {
    const uint32_t tbase = smb + (uint32_t)t * QTS * 2;
    const __half* g = &src[t][(long)(row0[t] + lrow) * HDIM + lcol];
#pragma unroll
    for (int i = 0; i < 4; i++)
      cp_async16(tbase + (uint32_t)(lrow * QLDQ + lcol + i * 8) * 2, g + i * 8);
  }
  asm volatile("cp.async.commit_group;" ::: "memory");

  float c[2][8][4];
#pragma unroll
  for (int mi = 0; mi < 2; mi++)
#pragma unroll
    for (int ni = 0; ni < 8; ni++)
#pragma unroll
      for (int j = 0; j < 4; j++) c[mi][ni][j] = 0.f;

  const uint32_t a_off = ((warp_m * 32 + (lane & 15)) * QLDQ + ((lane >> 4) << 3)) * 2;
  const uint32_t b_off = ((warp_n * 64 + (lane & 15)) * QLDQ + ((lane >> 4) << 3)) * 2;

  const int pa[3] = {0, 0, 2};
  const int pb[3] = {1, 3, 1};

  asm volatile("cp.async.wait_group 1;" ::: "memory");
  __syncthreads();

#pragma unroll 1
  for (int ph = 0; ph < 3; ph++) {
    if (ph == 1) {
      asm volatile("cp.async.wait_group 0;" ::: "memory");
      __syncthreads();
    }
    const uint32_t ab = smb + (uint32_t)pa[ph] * QTS * 2;
    const uint32_t bb = smb + (uint32_t)pb[ph] * QTS * 2;
#pragma unroll
    for (int ks = 0; ks < 4; ks++) {
      uint32_t a[2][4];
#pragma unroll
      for (int mi = 0; mi < 2; mi++)
        ldsm_x4(a[mi][0], a[mi][1], a[mi][2], a[mi][3],
                ab + a_off + (mi * 16 * QLDQ + ks * 16) * 2);
#pragma unroll
      for (int nig = 0; nig < 4; nig++) {
        uint32_t b0, b1, b2, b3;
        ldsm_x4(b0, b1, b2, b3, bb + b_off + (nig * 16 * QLDQ + ks * 16) * 2);
#pragma unroll
        for (int mi = 0; mi < 2; mi++) {
          mma16816(c[mi][2 * nig + 0], a[mi], b0, b2);
          mma16816(c[mi][2 * nig + 1], a[mi], b1, b3);
        }
      }
    }
  }

  // score stores: streaming (evict-first) so Q/K operand lines keep L2 residency
  float* C = g_attn + (long long)head * SEQ * SEQ;
#pragma unroll
  for (int mi = 0; mi < 2; mi++) {
    const int r = m0 + warp_m * 32 + mi * 16 + (lane >> 2);
#pragma unroll
    for (int ni = 0; ni < 8; ni++) {
      const int col = n0 + warp_n * 64 + ni * 8 + 2 * (lane & 3);
      __stcs((float2*)&C[(long)r * SEQ + col],
             make_float2(c[mi][ni][0], c[mi][ni][1]));
      __stcs((float2*)&C[(long)(r + 8) * SEQ + col],
             make_float2(c[mi][ni][2], c[mi][ni][3]));
    }
  }
}

// ---------------------------------------------------------------------------
// Stage 3: exact fp32 k-th largest + masked softmax -> fp16 P.
// (R6 algorithm, frozen; loads/stores carry streaming hints only)
// ---------------------------------------------------------------------------
__global__ void __launch_bounds__(256) select_softmax_kernel() {
  const float* row = g_attn + (long long)blockIdx.x * SEQ;
  __half* rowp = g_p + (long long)blockIdx.x * SEQ;

  __shared__ int hist[256];
  __shared__ int scan[256];
  __shared__ float redf[8];
  __shared__ float s_max, s_inv;
  __shared__ int s_bucket, s_r, s_cnt;
  __shared__ unsigned s_thr;
  __shared__ unsigned cand[2048];

  const int tid = threadIdx.x;
  const int warp = tid >> 5, lane = tid & 31;

  float4 va = __ldcs((const float4*)&row[tid * 8]);
  float4 vb = __ldcs((const float4*)&row[tid * 8 + 4]);
  float myv[8] = {va.x, va.y, va.z, va.w, vb.x, vb.y, vb.z, vb.w};

  float mx = myv[0];
#pragma unroll
  for (int i = 1; i < 8; i++) mx = fmaxf(mx, myv[i]);
#pragma unroll
  for (int o = 16; o > 0; o >>= 1) mx = fmaxf(mx, __shfl_xor_sync(~0u, mx, o));
  if (lane == 0) redf[warp] = mx;
  hist[tid] = 0;
  __syncthreads();
  if (warp == 0) {
    float m2 = (lane < 8) ? redf[lane] : -3.4e38f;
#pragma unroll
    for (int o = 4; o > 0; o >>= 1) m2 = fmaxf(m2, __shfl_xor_sync(~0u, m2, o));
    if (lane == 0) s_max = m2;
  }

  unsigned key[8];
#pragma unroll
  for (int i = 0; i < 8; i++) {
    int b = __float_as_int(myv[i]);
    key[i] = (unsigned)b ^ ((b < 0) ? 0xFFFFFFFFu : 0x80000000u);
  }

#pragma unroll
  for (int i = 0; i < 8; i++) atomicAdd(&hist[key[i] >> 24], 1);
  __syncthreads();

  scan[tid] = hist[tid];
  __syncthreads();
#pragma unroll
  for (int off = 1; off < 256; off <<= 1) {
    int t = scan[tid] + ((tid + off < 256) ? scan[tid + off] : 0);
    __syncthreads();
    scan[tid] = t;
    __syncthreads();
  }
  if (scan[tid] >= KSEL && (tid == 255 || scan[tid + 1] < KSEL)) {
    s_bucket = tid;
    s_r = KSEL - ((tid == 255) ? 0 : scan[tid + 1]);
    s_cnt = 0;
  }
  __syncthreads();
  const unsigned bucket = (unsigned)s_bucket;

#pragma unroll
  for (int i = 0; i < 8; i++)
    if ((key[i] >> 24) == bucket) cand[atomicAdd(&s_cnt, 1)] = key[i];
  __syncthreads();

  if (warp == 0) {
    const int c = s_cnt;
    int r = s_r;
    unsigned P = bucket << 24;
#pragma unroll 1
    for (int b = 23; b >= 0; b--) {
      const unsigned want = (P | (1u << b)) >> b;
      int cnt = 0;
      for (int i = lane; i < c; i += 32)
        if ((cand[i] >> b) == want) cnt++;
#pragma unroll
      for (int o = 16; o > 0; o >>= 1) cnt += __shfl_xor_sync(~0u, cnt, o);
      if (r <= cnt) P |= 1u << b;
      else r -= cnt;
    }
    if (lane == 0) s_thr = P;
  }
  __syncthreads();
  const unsigned thr = s_thr;
  const float rowmax = s_max;

  const float nm = -rowmax * L2E;
  float myp[8];
  float esum = 0.f;
#pragma unroll
  for (int i = 0; i < 8; i++) {
    float e = (key[i] >= thr) ? fast_exp2(fmaf(myv[i], L2E, nm)) : 0.f;
    myp[i] = e;
    esum += e;
  }
#pragma unroll
  for (int o = 16; o > 0; o >>= 1) esum += __shfl_xor_sync(~0u, esum, o);
  if (lane == 0) redf[warp] = esum;
  __syncthreads();
  if (warp == 0) {
    float z = (lane < 8) ? redf[lane] : 0.f;
#pragma unroll
    for (int o = 4; o > 0; o >>= 1) z += __shfl_xor_sync(~0u, z, o);
    if (lane == 0) s_inv = 1.f / z;
  }
  __syncthreads();
  const float inv = s_inv;

  union { __half2 h[4]; uint4 u; } pk;
#pragma unroll
  for (int i = 0; i < 4; i++)
    pk.h[i] = __floats2half2_rn(myp[2 * i] * inv, myp[2 * i + 1] * inv);
  __stcs((uint4*)&rowp[tid * 8], pk.u);
}

// ---------------------------------------------------------------------------
// Stage 4: P@V per head, fp16 HMMA, cp.async 2-stage ring (R14-proven).
// ---------------------------------------------------------------------------
__global__ void __launch_bounds__(256) pv_hmma_kernel() {
  constexpr int NIT = SEQ / 64;  // 32
  extern __shared__ __half pvsm[];

  const int head = blockIdx.y;
  const int m0 = blockIdx.x * 128;
  const __half* __restrict__ P = g_p + (long long)head * SEQ * SEQ;
  const __half* __restrict__ V = g_vh + (long)head * SEQ * HDIM;

  const int tid = threadIdx.x;
  const int warp = tid >> 5, lane = tid & 31;
  const int wm0 = warp * 16;

  float c[8][4];
#pragma unroll
  for (int i = 0; i < 8; i++)
#pragma unroll
    for (int j = 0; j < 4; j++) c[i][j] = 0.f;

  const int pr = tid >> 3, pc = (tid & 7) << 3;
  const uint32_t smb = (uint32_t)__cvta_generic_to_shared(pvsm);

  auto issue = [&](int stage, int k0) {
    const uint32_t pb = smb + (uint32_t)stage * PSTG * 2;
    const uint32_t vb = pb + (uint32_t)PTS * 2;
#pragma unroll
    for (int l = 0; l < 4; l++)
      cp_async16(pb + (uint32_t)((pr + 32 * l) * PLDP + pc) * 2,
                 &P[(long)(m0 + pr + 32 * l) * SEQ + k0 + pc]);
#pragma unroll
    for (int l = 0; l < 2; l++)
      cp_async16(vb + (uint32_t)((pr + 32 * l) * PLDP + pc) * 2,
                 &V[(long)(k0 + pr + 32 * l) * HDIM + pc]);
  };

  issue(0, 0);
  asm volatile("cp.async.commit_group;" ::: "memory");

  const uint32_t a_off = ((wm0 + (lane & 15)) * PLDP + ((lane >> 4) << 3)) * 2;
  const uint32_t b_row = (lane & 7) + (lane & 8);
  const uint32_t b_off = (b_row * PLDP + ((lane & 16) >> 1)) * 2;

#pragma unroll 1
  for (int it = 0; it < NIT; it++) {
    if (it + 1 < NIT) {
      issue((it + 1) & 1, (it + 1) * 64);
      asm volatile("cp.async.commit_group;" ::: "memory");
      asm volatile("cp.async.wait_group 1;" ::: "memory");
    } else {
      asm volatile("cp.async.wait_group 0;" ::: "memory");
    }
    __syncthreads();

    const uint32_t so = (uint32_t)(it & 1) * PSTG * 2;
    const uint32_t a_base = smb + so + a_off;
    const uint32_t b_base = smb + so + (uint32_t)PTS * 2 + b_off;

#pragma unroll
    for (int ks = 0; ks < 4; ks++) {
      uint32_t a[4];
      ldsm_x4(a[0], a[1], a[2], a[3], a_base + ks * 16 * 2);
#pragma unroll
      for (int g = 0; g < 4; g++) {
        uint32_t b0, b1, b2, b3;
        ldsm_x4_t(b0, b1, b2, b3, b_base + (ks * 16 * PLDP + g * 16) * 2);
        mma16816(c[2 * g + 0], a, b0, b1);
        mma16816(c[2 * g + 1], a, b2, b3);
      }
    }
    __syncthreads();
  }

  // epilogue -> ctx fp16 hi+lo [B,S,H]
  const int b = head / NH, h = head - b * NH;
  const int r0 = lane >> 2, col0 = (lane & 3) * 2;
  const long rowbase0 = (long)(b * SEQ + m0 + wm0 + r0) * HID + h * HDIM;
  const long rowbase1 = rowbase0 + 8L * HID;
#pragma unroll
  for (int nt = 0; nt < 8; nt++) {
    const int n = nt * 8 + col0;
    {
      float v0 = c[nt][0], v1 = c[nt][1];
      __half h0 = __float2half_rn(v0), h1 = __float2half_rn(v1);
      *(__half2*)&g_ctxh[rowbase0 + n] = __halves2half2(h0, h1);
      *(__half2*)&g_ctxl[rowbase0 + n] =
          __floats2half2_rn(v0 - __half2float(h0), v1 - __half2float(h1));
    }
    {
      float v0 = c[nt][2], v1 = c[nt][3];
      __half h0 = __float2half_rn(v0), h1 = __float2half_rn(v1);
      *(__half2*)&g_ctxh[rowbase1 + n] = __halves2half2(h0, h1);
      *(__half2*)&g_ctxl[rowbase1 + n] =
          __floats2half2_rn(v0 - __half2float(h0), v1 - __half2float(h1));
    }
  }
}

// ---------------------------------------------------------------------------
extern "C" void kernel_launch(void* const* d_in, const int* in_sizes, int n_in,
                              void* d_out, int out_size) {
  const float* hidden = (const float*)d_in[0];
  const float* qkv_w  = (const float*)d_in[1];
  const float* qkv_b  = (const float*)d_in[2];
  const float* proj_w = (const float*)d_in[3];
  const float* proj_b = (const float*)d_in[4];
  float* out = (float*)d_out;

  // dynamic smem caps (host-side attributes; idempotent)
  cudaFuncSetAttribute(hgemm_comp<HID, CfgQKV3>,
                       cudaFuncAttributeMaxDynamicSharedMemorySize, GSMEM);
  cudaFuncSetAttribute(hgemm_comp<HID, CfgProj3>,
                       cudaFuncAttributeMaxDynamicSharedMemorySize, GSMEM);
  cudaFuncSetAttribute(qk_comp_kernel,
                       cudaFuncAttributeMaxDynamicSharedMemorySize, QK_SMEM);
  cudaFuncSetAttribute(pv_hmma_kernel,
                       cudaFuncAttributeMaxDynamicSharedMemorySize, PV_SMEM);

  // 0) operand splits
  {
    __half *hidh, *hidl, *wqh, *wql, *wph, *wpl;
    cudaGetSymbolAddress((void**)&hidh, g_hidh);
    cudaGetSymbolAddress((void**)&hidl, g_hidl);
    cudaGetSymbolAddress((void**)&wqh, g_wqh);
    cudaGetSymbolAddress((void**)&wql, g_wql);
    cudaGetSymbolAddress((void**)&wph, g_wph);
    cudaGetSymbolAddress((void**)&wpl, g_wpl);
    int n1 = BATCH * SEQ * HID / 4;
    int n2 = 3 * HID * HID / 4;
    int n3 = HID * HID / 4;
    split_kernel<<<(n1 + 255) / 256, 256>>>(hidden, hidh, hidl, n1);
    split_kernel<<<(n2 + 255) / 256, 256>>>(qkv_w, wqh, wql, n2);
    split_kernel<<<(n3 + 255) / 256, 256>>>(proj_w, wph, wpl, n3);
  }

  // 1) QKV comp-HMMA (cp.async double-buffered)
  hgemm_comp<HID><<<dim3((3 * HID) / 128, (BATCH * SEQ) / 128), 256, GSMEM>>>(
      CfgQKV3{qkv_b});

  // 2) QK^T comp-HMMA per head (R11 cp.async pipelined, .cs score stores)
  qk_comp_kernel<<<dim3(SEQ / 128, SEQ / 128, HEADS), 256, QK_SMEM>>>();

  // 3) exact select + softmax (R6 frozen; .cs streaming loads/stores)
  select_softmax_kernel<<<dim3(HEADS * SEQ), 256>>>();

  // 4) PV HMMA (cp.async 2-stage ring)
  pv_hmma_kernel<<<dim3(SEQ / 128, HEADS), 256, PV_SMEM>>>();

  // 5) proj comp-HMMA (cp.async double-buffered)
  hgemm_comp<HID><<<dim3(HID / 128, (BATCH * SEQ) / 128), 256, GSMEM>>>(
      CfgProj3{proj_b, out});
}

// round 16
// speedup vs baseline: 1.0082x; 1.0082x over previous
#include <cuda_runtime.h>
#include <cuda_fp16.h>
#include <cstdint>

// VisionDynamicSparseAttention pipeline (round 16 = R15 + 2-rows-per-block select):
//  0) split kernels: hidden/qkv_w/proj_w -> fp16 hi+lo pairs
//  1) QKV via compensated fp16 HMMA, cp.async double-buffered (+bias)
//  2) Q@K^T comp-HMMA (R11 pipeline); .cs score stores
//  3) select: exact fp32 k-th largest (R6 algorithm per row, 2 rows/block
//     sharing barriers) + masked softmax -> g_p fp16
//  4) PV fp16 HMMA, cp.async 2-stage ring -> ctx fp16 hi+lo
//  5) proj via compensated fp16 HMMA, cp.async (+bias) -> d_out fp32

namespace {
constexpr int NH    = 12;
constexpr int HDIM  = 64;
constexpr int BATCH = 2;
constexpr int SEQ   = 2048;
constexpr int HID   = 768;
constexpr int HEADS = BATCH * NH;   // 24
constexpr int KSEL  = 1024;
constexpr float L2E = 1.4426950408889634f;
// hgemm tiling
constexpr int GLDA = 40;                  // halves pitch (80B rows)
constexpr int GTS  = 128 * GLDA;          // halves per tensor tile
constexpr int GSMEM = 2 * 4 * GTS * 2;    // bytes: 2 stages x 4 tensors
// qk tiling (R11)
constexpr int QLDQ = 72;                  // halves pitch (144B rows)
constexpr int QTS  = 128 * QLDQ;          // halves per tile
constexpr int QK_SMEM = 4 * QTS * 2;      // bytes: Qh,Kh,Ql,Kl resident (73728)
// pv tiling (R14)
constexpr int PLDP = 72;                  // halves pitch
constexpr int PTS  = 128 * PLDP;          // P tile halves
constexpr int VTS  = 64 * PLDP;           // V tile halves
constexpr int PSTG = PTS + VTS;           // halves per stage
constexpr int PV_SMEM = 2 * PSTG * 2;     // bytes (55296)
}

// fp16 hi/lo operand copies
__device__ __half g_hidh[BATCH * SEQ * HID];
__device__ __half g_hidl[BATCH * SEQ * HID];
__device__ __half g_wqh[3 * HID * HID];
__device__ __half g_wql[3 * HID * HID];
__device__ __half g_wph[HID * HID];
__device__ __half g_wpl[HID * HID];
// per-head q/k (hi+lo), v
__device__ __half g_qh[HEADS * SEQ * HDIM];
__device__ __half g_ql[HEADS * SEQ * HDIM];
__device__ __half g_kh[HEADS * SEQ * HDIM];
__device__ __half g_kl[HEADS * SEQ * HDIM];
__device__ __half g_vh[HEADS * SEQ * HDIM];
// attention
__device__ float  g_attn[(long long)HEADS * SEQ * SEQ];  // fp32 scores
__device__ __half g_p[(long long)HEADS * SEQ * SEQ];     // fp16 probs
// context (hi+lo for proj A operand)
__device__ __half g_ctxh[BATCH * SEQ * HID];
__device__ __half g_ctxl[BATCH * SEQ * HID];

// FMA-only exp2 (range-reduced deg-5; rel err ~2.4e-6)
__device__ __forceinline__ float fast_exp2(float y) {
  float t = y + 12582912.0f;
  int   i = __float_as_int(t);
  float f = y - (t - 12582912.0f);
  float p = 1.3333558146e-3f;
  p = fmaf(p, f, 9.6181291918e-3f);
  p = fmaf(p, f, 5.5504108665e-2f);
  p = fmaf(p, f, 2.4022650696e-1f);
  p = fmaf(p, f, 6.9314718056e-1f);
  p = fmaf(p, f, 1.0f);
  return __int_as_float(__float_as_int(p) + (i << 23));
}

// ---------------------------------------------------------------------------
// split: fp32 -> fp16 hi + lo residual
// ---------------------------------------------------------------------------
__global__ void __launch_bounds__(256) split_kernel(const float* __restrict__ src,
                                                    __half* __restrict__ hi,
                                                    __half* __restrict__ lo, int n4) {
  int i = blockIdx.x * blockDim.x + threadIdx.x;
  if (i >= n4) return;
  float4 v = ((const float4*)src)[i];
  __half hx = __float2half_rn(v.x), hy = __float2half_rn(v.y);
  __half hz = __float2half_rn(v.z), hw = __float2half_rn(v.w);
  union { __half2 h2[2]; uint2 u; } H, L;
  H.h2[0] = __halves2half2(hx, hy);
  H.h2[1] = __halves2half2(hz, hw);
  L.h2[0] = __floats2half2_rn(v.x - __half2float(hx), v.y - __half2float(hy));
  L.h2[1] = __floats2half2_rn(v.z - __half2float(hz), v.w - __half2float(hw));
  ((uint2*)hi)[i] = H.u;
  ((uint2*)lo)[i] = L.u;
}

// ---------------------------------------------------------------------------
// HMMA / async primitives
// ---------------------------------------------------------------------------
__device__ __forceinline__ void ldsm_x4(uint32_t& r0, uint32_t& r1, uint32_t& r2,
                                        uint32_t& r3, uint32_t saddr) {
  asm volatile("ldmatrix.sync.aligned.m8n8.x4.shared.b16 {%0,%1,%2,%3}, [%4];"
               : "=r"(r0), "=r"(r1), "=r"(r2), "=r"(r3) : "r"(saddr));
}
__device__ __forceinline__ void ldsm_x4_t(uint32_t& r0, uint32_t& r1, uint32_t& r2,
                                          uint32_t& r3, uint32_t saddr) {
  asm volatile("ldmatrix.sync.aligned.m8n8.x4.trans.shared.b16 {%0,%1,%2,%3}, [%4];"
               : "=r"(r0), "=r"(r1), "=r"(r2), "=r"(r3) : "r"(saddr));
}
__device__ __forceinline__ void mma16816(float* c, const uint32_t a[4],
                                         uint32_t b0, uint32_t b1) {
  asm volatile(
      "mma.sync.aligned.m16n8k16.row.col.f32.f16.f16.f32 "
      "{%0,%1,%2,%3}, {%4,%5,%6,%7}, {%8,%9}, {%0,%1,%2,%3};"
      : "+f"(c[0]), "+f"(c[1]), "+f"(c[2]), "+f"(c[3])
      : "r"(a[0]), "r"(a[1]), "r"(a[2]), "r"(a[3]), "r"(b0), "r"(b1));
}
__device__ __forceinline__ void cp_async16(uint32_t saddr, const void* g) {
  asm volatile("cp.async.cg.shared.global [%0], [%1], 16;" :: "r"(saddr), "l"(g));
}

// ---------------------------------------------------------------------------
// Compensated fp16 GEMM, cp.async 2-stage (R8/R10-proven).
// ---------------------------------------------------------------------------
template <int KDIM, class Cfg>
__global__ void __launch_bounds__(256) hgemm_comp(Cfg cfg) {
  constexpr int BK = 32;
  constexpr int NIT = KDIM / BK;
  extern __shared__ __half dynsm[];

  const __half* __restrict__ src[4] = {cfg.Ah(), cfg.Al(), cfg.Bh(), cfg.Bl()};

  const int tid = threadIdx.x;
  const int warp = tid >> 5, lane = tid & 31;
  const int warp_m = warp >> 1, warp_n = warp & 1;
  const int m0 = blockIdx.y * 128;
  const int n0 = blockIdx.x * 128;
  const int row0[4] = {m0, m0, n0, n0};

  const int lr = tid >> 2;
  const int lc = (tid & 3) << 3;

  const uint32_t sm_base = (uint32_t)__cvta_generic_to_shared(dynsm);

  float c[2][8][4];
#pragma unroll
  for (int mi = 0; mi < 2; mi++)
#pragma unroll
    for (int ni = 0; ni < 8; ni++)
#pragma unroll
      for (int j = 0; j < 4; j++) c[mi][ni][j] = 0.f;

  auto issue = [&](int stage, int k0) {
#pragma unroll
    for (int t = 0; t < 4; t++) {
      const uint32_t tbase = sm_base + (uint32_t)(stage * 4 + t) * GTS * 2;
#pragma unroll
      for (int h = 0; h < 2; h++) {
        const int r = lr + 64 * h;
        cp_async16(tbase + (uint32_t)(r * GLDA + lc) * 2,
                   &src[t][(long)(row0[t] + r) * KDIM + k0 + lc]);
      }
    }
  };

  issue(0, 0);
  asm volatile("cp.async.commit_group;" ::: "memory");

  const uint32_t a_off = ((warp_m * 32 + (lane & 15)) * GLDA + ((lane >> 4) << 3)) * 2;
  const uint32_t b_off = ((warp_n * 64 + (lane & 15)) * GLDA + ((lane >> 4) << 3)) * 2;

#pragma unroll 1
  for (int it = 0; it < NIT; it++) {
    if (it + 1 < NIT) {
      issue((it + 1) & 1, (it + 1) * BK);
      asm volatile("cp.async.commit_group;" ::: "memory");
      asm volatile("cp.async.wait_group 1;" ::: "memory");
    } else {
      asm volatile("cp.async.wait_group 0;" ::: "memory");
    }
    __syncthreads();

    const int st = it & 1;
    const uint32_t ah_b = sm_base + (uint32_t)(st * 4 + 0) * GTS * 2;
    const uint32_t al_b = sm_base + (uint32_t)(st * 4 + 1) * GTS * 2;
    const uint32_t bh_b = sm_base + (uint32_t)(st * 4 + 2) * GTS * 2;
    const uint32_t bl_b = sm_base + (uint32_t)(st * 4 + 3) * GTS * 2;

#pragma unroll
    for (int ks = 0; ks < 2; ks++) {
      uint32_t ah[2][4], al[2][4];
#pragma unroll
      for (int mi = 0; mi < 2; mi++) {
        ldsm_x4(ah[mi][0], ah[mi][1], ah[mi][2], ah[mi][3],
                ah_b + a_off + (mi * 16 * GLDA + ks * 16) * 2);
        ldsm_x4(al[mi][0], al[mi][1], al[mi][2], al[mi][3],
                al_b + a_off + (mi * 16 * GLDA + ks * 16) * 2);
      }
#pragma unroll
      for (int nig = 0; nig < 4; nig++) {
        uint32_t bh0, bh1, bh2, bh3, bl0, bl1, bl2, bl3;
        ldsm_x4(bh0, bh1, bh2, bh3, bh_b + b_off + (nig * 16 * GLDA + ks * 16) * 2);
        ldsm_x4(bl0, bl1, bl2, bl3, bl_b + b_off + (nig * 16 * GLDA + ks * 16) * 2);
#pragma unroll
        for (int mi = 0; mi < 2; mi++) {
          mma16816(c[mi][2 * nig + 0], ah[mi], bh0, bh2);
          mma16816(c[mi][2 * nig + 1], ah[mi], bh1, bh3);
          mma16816(c[mi][2 * nig + 0], ah[mi], bl0, bl2);
          mma16816(c[mi][2 * nig + 1], ah[mi], bl1, bl3);
          mma16816(c[mi][2 * nig + 0], al[mi], bh0, bh2);
          mma16816(c[mi][2 * nig + 1], al[mi], bh1, bh3);
        }
      }
    }
    __syncthreads();
  }
  cfg.epi(c, m0, n0, warp_m, warp_n, lane);
}

// ---------------- Stage 1: QKV (comp-HMMA) ----------------
struct CfgQKV3 {
  const float* bias;
  __device__ __forceinline__ const __half* Ah() const { return g_hidh; }
  __device__ __forceinline__ const __half* Al() const { return g_hidl; }
  __device__ __forceinline__ const __half* Bh() const { return g_wqh; }
  __device__ __forceinline__ const __half* Bl() const { return g_wql; }
  __device__ __forceinline__ void handle(int m, int n, float v0, float v1) const {
    const int b = m >> 11, s = m & (SEQ - 1);
    const int sec = n / HID;
    const int rem = n - sec * HID;
    const int h = rem >> 6, d = rem & 63;
    const long base = ((long)((b * NH + h) * SEQ + s)) * HDIM + d;
    v0 += bias[n];
    v1 += bias[n + 1];
    if (sec == 0) { v0 *= 0.125f; v1 *= 0.125f; }
    __half h0 = __float2half_rn(v0), h1 = __float2half_rn(v1);
    __half2 hi = __halves2half2(h0, h1);
    if (sec == 2) {
      *(__half2*)&g_vh[base] = hi;
      return;
    }
    __half2 lo = __floats2half2_rn(v0 - __half2float(h0), v1 - __half2float(h1));
    if (sec == 0) {
      *(__half2*)&g_qh[base] = hi;
      *(__half2*)&g_ql[base] = lo;
    } else {
      *(__half2*)&g_kh[base] = hi;
      *(__half2*)&g_kl[base] = lo;
    }
  }
  __device__ __forceinline__ void epi(const float c[2][8][4], int m0, int n0,
                                      int warp_m, int warp_n, int lane) const {
#pragma unroll
    for (int mi = 0; mi < 2; mi++) {
      const int r = m0 + warp_m * 32 + mi * 16 + (lane >> 2);
#pragma unroll
      for (int ni = 0; ni < 8; ni++) {
        const int n = n0 + warp_n * 64 + ni * 8 + 2 * (lane & 3);
        handle(r, n, c[mi][ni][0], c[mi][ni][1]);
        handle(r + 8, n, c[mi][ni][2], c[mi][ni][3]);
      }
    }
  }
};

// ---------------- Stage 5: proj (comp-HMMA) ----------------
struct CfgProj3 {
  const float* bias;
  float* out;
  __device__ __forceinline__ const __half* Ah() const { return g_ctxh; }
  __device__ __forceinline__ const __half* Al() const { return g_ctxl; }
  __device__ __forceinline__ const __half* Bh() const { return g_wph; }
  __device__ __forceinline__ const __half* Bl() const { return g_wpl; }
  __device__ __forceinline__ void epi(const float c[2][8][4], int m0, int n0,
                                      int warp_m, int warp_n, int lane) const {
#pragma unroll
    for (int mi = 0; mi < 2; mi++) {
      const int r = m0 + warp_m * 32 + mi * 16 + (lane >> 2);
#pragma unroll
      for (int ni = 0; ni < 8; ni++) {
        const int n = n0 + warp_n * 64 + ni * 8 + 2 * (lane & 3);
        const float b0 = bias[n], b1 = bias[n + 1];
        *(float2*)&out[(long)r * HID + n] =
            make_float2(c[mi][ni][0] + b0, c[mi][ni][1] + b1);
        *(float2*)&out[(long)(r + 8) * HID + n] =
            make_float2(c[mi][ni][2] + b0, c[mi][ni][3] + b1);
      }
    }
  }
};

// ---------------------------------------------------------------------------
// Stage 2: compensated QK^T, cp.async pipelined (R11); .cs score stores.
// ---------------------------------------------------------------------------
__global__ void __launch_bounds__(256) qk_comp_kernel() {
  extern __shared__ __half qsm[];

  const int head = blockIdx.z;
  const int m0 = blockIdx.y * 128;
  const int n0 = blockIdx.x * 128;
  const long qoff = (long)head * SEQ * HDIM;

  const int tid = threadIdx.x;
  const int warp = tid >> 5, lane = tid & 31;
  const int warp_m = warp >> 1, warp_n = warp & 1;

  // tile order: 0=Qh, 1=Kh (group A); 2=Ql, 3=Kl (group B)
  const __half* __restrict__ src[4] = {g_qh + qoff, g_kh + qoff,
                                       g_ql + qoff, g_kl + qoff};
  const int row0[4] = {m0, n0, m0, n0};

  const int lrow = tid >> 1;
  const int lcol = (tid & 1) * 32;
  const uint32_t smb = (uint32_t)__cvta_generic_to_shared(qsm);

#pragma unroll
  for (int t = 0; t < 2; t++) {
    const uint32_t tbase = smb + (uint32_t)t * QTS * 2;
    const __half* g = &src[t][(long)(row0[t] + lrow) * HDIM + lcol];
#pragma unroll
    for (int i = 0; i < 4; i++)
      cp_async16(tbase + (uint32_t)(lrow * QLDQ + lcol + i * 8) * 2, g + i * 8);
  }
  asm volatile("cp.async.commit_group;" ::: "memory");
#pragma unroll
  for (int t = 2; t < 4; t++) {
    const uint32_t tbase = smb + (uint32_t)t * QTS * 2;
    const __half* g = &src[t][(long)(row0[t] + lrow) * HDIM + lcol];
#pragma unroll
    for (int i = 0; i < 4; i++)
      cp_async16(tbase + (uint32_t)(lrow * QLDQ + lcol + i * 8) * 2, g + i * 8);
  }
  asm volatile("cp.async.commit_group;" ::: "memory");

  float c[2][8][4];
#pragma unroll
  for (int mi = 0; mi < 2; mi++)
#pragma unroll
    for (int ni = 0; ni < 8; ni++)
#pragma unroll
      for (int j = 0; j < 4; j++) c[mi][ni][j] = 0.f;

  const uint32_t a_off = ((warp_m * 32 + (lane & 15)) * QLDQ + ((lane >> 4) << 3)) * 2;
  const uint32_t b_off = ((warp_n * 64 + (lane & 15)) * QLDQ + ((lane >> 4) << 3)) * 2;

  const int pa[3] = {0, 0, 2};
  const int pb[3] = {1, 3, 1};

  asm volatile("cp.async.wait_group 1;" ::: "memory");
  __syncthreads();

#pragma unroll 1
  for (int ph = 0; ph < 3; ph++) {
    if (ph == 1) {
      asm volatile("cp.async.wait_group 0;" ::: "memory");
      __syncthreads();
    }
    const uint32_t ab = smb + (uint32_t)pa[ph] * QTS * 2;
    const uint32_t bb = smb + (uint32_t)pb[ph] * QTS * 2;
#pragma unroll
    for (int ks = 0; ks < 4; ks++) {
      uint32_t a[2][4];
#pragma unroll
      for (int mi = 0; mi < 2; mi++)
        ldsm_x4(a[mi][0], a[mi][1], a[mi][2], a[mi][3],
                ab + a_off + (mi * 16 * QLDQ + ks * 16) * 2);
#pragma unroll
      for (int nig = 0; nig < 4; nig++) {
        uint32_t b0, b1, b2, b3;
        ldsm_x4(b0, b1, b2, b3, bb + b_off + (nig * 16 * QLDQ + ks * 16) * 2);
#pragma unroll
        for (int mi = 0; mi < 2; mi++) {
          mma16816(c[mi][2 * nig + 0], a[mi], b0, b2);
          mma16816(c[mi][2 * nig + 1], a[mi], b1, b3);
        }
      }
    }
  }

  float* C = g_attn + (long long)head * SEQ * SEQ;
#pragma unroll
  for (int mi = 0; mi < 2; mi++) {
    const int r = m0 + warp_m * 32 + mi * 16 + (lane >> 2);
#pragma unroll
    for (int ni = 0; ni < 8; ni++) {
      const int col = n0 + warp_n * 64 + ni * 8 + 2 * (lane & 3);
      __stcs((float2*)&C[(long)r * SEQ + col],
             make_float2(c[mi][ni][0], c[mi][ni][1]));
      __stcs((float2*)&C[(long)(r + 8) * SEQ + col],
             make_float2(c[mi][ni][2], c[mi][ni][3]));
    }
  }
}

// ---------------------------------------------------------------------------
// Stage 3: exact fp32 k-th largest + masked softmax -> fp16 P.
// R6 algorithm per row, TWO rows per 512-thread block sharing barriers.
// g = row half (tid>>8), t = tid within half (0..255).
// ---------------------------------------------------------------------------
__global__ void __launch_bounds__(512) select_softmax_kernel() {
  const int tid = threadIdx.x;
  const int g = tid >> 8;         // which row this thread serves
  const int t = tid & 255;        // index within the row group
  const int warp = t >> 5, lane = tid & 31;
  const long long row = (long long)blockIdx.x * 2 + g;
  const float* srow = g_attn + row * SEQ;
  __half* rowp = g_p + row * SEQ;

  __shared__ int hist[2][256];
  __shared__ int scan[2][256];
  __shared__ float redf[2][8];
  __shared__ float s_max[2], s_inv[2];
  __shared__ int s_bucket[2], s_r[2], s_cnt[2];
  __shared__ unsigned s_thr[2];
  __shared__ unsigned cand[2][2048];

  float4 va = __ldcs((const float4*)&srow[t * 8]);
  float4 vb = __ldcs((const float4*)&srow[t * 8 + 4]);
  float myv[8] = {va.x, va.y, va.z, va.w, vb.x, vb.y, vb.z, vb.w};

  // row max (warps are wholly within one row half)
  float mx = myv[0];
#pragma unroll
  for (int i = 1; i < 8; i++) mx = fmaxf(mx, myv[i]);
#pragma unroll
  for (int o = 16; o > 0; o >>= 1) mx = fmaxf(mx, __shfl_xor_sync(~0u, mx, o));
  if (lane == 0) redf[g][warp] = mx;
  hist[g][t] = 0;
  __syncthreads();
  if (warp == 0) {  // warps 0 (row 0) and 8 (row 1)
    float m2 = (lane < 8) ? redf[g][lane] : -3.4e38f;
#pragma unroll
    for (int o = 4; o > 0; o >>= 1) m2 = fmaxf(m2, __shfl_xor_sync(~0u, m2, o));
    if (lane == 0) s_max[g] = m2;
  }

  unsigned key[8];
#pragma unroll
  for (int i = 0; i < 8; i++) {
    int b = __float_as_int(myv[i]);
    key[i] = (unsigned)b ^ ((b < 0) ? 0xFFFFFFFFu : 0x80000000u);
  }

#pragma unroll
  for (int i = 0; i < 8; i++) atomicAdd(&hist[g][key[i] >> 24], 1);
  __syncthreads();

  scan[g][t] = hist[g][t];
  __syncthreads();
#pragma unroll
  for (int off = 1; off < 256; off <<= 1) {
    int v = scan[g][t] + ((t + off < 256) ? scan[g][t + off] : 0);
    __syncthreads();
    scan[g][t] = v;
    __syncthreads();
  }
  if (scan[g][t] >= KSEL && (t == 255 || scan[g][t + 1] < KSEL)) {
    s_bucket[g] = t;
    s_r[g] = KSEL - ((t == 255) ? 0 : scan[g][t + 1]);
    s_cnt[g] = 0;
  }
  __syncthreads();
  const unsigned bucket = (unsigned)s_bucket[g];

#pragma unroll
  for (int i = 0; i < 8; i++)
    if ((key[i] >> 24) == bucket) cand[g][atomicAdd(&s_cnt[g], 1)] = key[i];
  __syncthreads();

  if (warp == 0) {  // one warp per row half does its bitselect, in parallel
    const int c = s_cnt[g];
    int r = s_r[g];
    unsigned P = bucket << 24;
#pragma unroll 1
    for (int b = 23; b >= 0; b--) {
      const unsigned want = (P | (1u << b)) >> b;
      int cnt = 0;
      for (int i = lane; i < c; i += 32)
        if ((cand[g][i] >> b) == want) cnt++;
#pragma unroll
      for (int o = 16; o > 0; o >>= 1) cnt += __shfl_xor_sync(~0u, cnt, o);
      if (r <= cnt) P |= 1u << b;
      else r -= cnt;
    }
    if (lane == 0) s_thr[g] = P;
  }
  __syncthreads();
  const unsigned thr = s_thr[g];
  const float rowmax = s_max[g];

  const float nm = -rowmax * L2E;
  float myp[8];
  float esum = 0.f;
#pragma unroll
  for (int i = 0; i < 8; i++) {
    float e = (key[i] >= thr) ? fast_exp2(fmaf(myv[i], L2E, nm)) : 0.f;
    myp[i] = e;
    esum += e;
  }
#pragma unroll
  for (int o = 16; o > 0; o >>= 1) esum += __shfl_xor_sync(~0u, esum, o);
  if (lane == 0) redf[g][warp] = esum;
  __syncthreads();
  if (warp == 0) {
    float z = (lane < 8) ? redf[g][lane] : 0.f;
#pragma unroll
    for (int o = 4; o > 0; o >>= 1) z += __shfl_xor_sync(~0u, z, o);
    if (lane == 0) s_inv[g] = 1.f / z;
  }
  __syncthreads();
  const float inv = s_inv[g];

  union { __half2 h[4]; uint4 u; } pk;
#pragma unroll
  for (int i = 0; i < 4; i++)
    pk.h[i] = __floats2half2_rn(myp[2 * i] * inv, myp[2 * i + 1] * inv);
  __stcs((uint4*)&rowp[t * 8], pk.u);
}

// ---------------------------------------------------------------------------
// Stage 4: P@V per head, fp16 HMMA, cp.async 2-stage ring (R14-proven).
// ---------------------------------------------------------------------------
__global__ void __launch_bounds__(256) pv_hmma_kernel() {
  constexpr int NIT = SEQ / 64;  // 32
  extern __shared__ __half pvsm[];

  const int head = blockIdx.y;
  const int m0 = blockIdx.x * 128;
  const __half* __restrict__ P = g_p + (long long)head * SEQ * SEQ;
  const __half* __restrict__ V = g_vh + (long)head * SEQ * HDIM;

  const int tid = threadIdx.x;
  const int warp = tid >> 5, lane = tid & 31;
  const int wm0 = warp * 16;

  float c[8][4];
#pragma unroll
  for (int i = 0; i < 8; i++)
#pragma unroll
    for (int j = 0; j < 4; j++) c[i][j] = 0.f;

  const int pr = tid >> 3, pc = (tid & 7) << 3;
  const uint32_t smb = (uint32_t)__cvta_generic_to_shared(pvsm);

  auto issue = [&](int stage, int k0) {
    const uint32_t pb = smb + (uint32_t)stage * PSTG * 2;
    const uint32_t vb = pb + (uint32_t)PTS * 2;
#pragma unroll
    for (int l = 0; l < 4; l++)
      cp_async16(pb + (uint32_t)((pr + 32 * l) * PLDP + pc) * 2,
                 &P[(long)(m0 + pr + 32 * l) * SEQ + k0 + pc]);
#pragma unroll
    for (int l = 0; l < 2; l++)
      cp_async16(vb + (uint32_t)((pr + 32 * l) * PLDP + pc) * 2,
                 &V[(long)(k0 + pr + 32 * l) * HDIM + pc]);
  };

  issue(0, 0);
  asm volatile("cp.async.commit_group;" ::: "memory");

  const uint32_t a_off = ((wm0 + (lane & 15)) * PLDP + ((lane >> 4) << 3)) * 2;
  const uint32_t b_row = (lane & 7) + (lane & 8);
  const uint32_t b_off = (b_row * PLDP + ((lane & 16) >> 1)) * 2;

#pragma unroll 1
  for (int it = 0; it < NIT; it++) {
    if (it + 1 < NIT) {
      issue((it + 1) & 1, (it + 1) * 64);
      asm volatile("cp.async.commit_group;" ::: "memory");
      asm volatile("cp.async.wait_group 1;" ::: "memory");
    } else {
      asm volatile("cp.async.wait_group 0;" ::: "memory");
    }
    __syncthreads();

    const uint32_t so = (uint32_t)(it & 1) * PSTG * 2;
    const uint32_t a_base = smb + so + a_off;
    const uint32_t b_base = smb + so + (uint32_t)PTS * 2 + b_off;

#pragma unroll
    for (int ks = 0; ks < 4; ks++) {
      uint32_t a[4];
      ldsm_x4(a[0], a[1], a[2], a[3], a_base + ks * 16 * 2);
#pragma unroll
      for (int g = 0; g < 4; g++) {
        uint32_t b0, b1, b2, b3;
        ldsm_x4_t(b0, b1, b2, b3, b_base + (ks * 16 * PLDP + g * 16) * 2);
        mma16816(c[2 * g + 0], a, b0, b1);
        mma16816(c[2 * g + 1], a, b2, b3);
      }
    }
    __syncthreads();
  }

  // epilogue -> ctx fp16 hi+lo [B,S,H]
  const int b = head / NH, h = head - b * NH;
  const int r0 = lane >> 2, col0 = (lane & 3) * 2;
  const long rowbase0 = (long)(b * SEQ + m0 + wm0 + r0) * HID + h * HDIM;
  const long rowbase1 = rowbase0 + 8L * HID;
#pragma unroll
  for (int nt = 0; nt < 8; nt++) {
    const int n = nt * 8 + col0;
    {
      float v0 = c[nt][0], v1 = c[nt][1];
      __half h0 = __float2half_rn(v0), h1 = __float2half_rn(v1);
      *(__half2*)&g_ctxh[rowbase0 + n] = __halves2half2(h0, h1);
      *(__half2*)&g_ctxl[rowbase0 + n] =
          __floats2half2_rn(v0 - __half2float(h0), v1 - __half2float(h1));
    }
    {
      float v0 = c[nt][2], v1 = c[nt][3];
      __half h0 = __float2half_rn(v0), h1 = __float2half_rn(v1);
      *(__half2*)&g_ctxh[rowbase1 + n] = __halves2half2(h0, h1);
      *(__half2*)&g_ctxl[rowbase1 + n] =
          __floats2half2_rn(v0 - __half2float(h0), v1 - __half2float(h1));
    }
  }
}

// ---------------------------------------------------------------------------
extern "C" void kernel_launch(void* const* d_in, const int* in_sizes, int n_in,
                              void* d_out, int out_size) {
  const float* hidden = (const float*)d_in[0];
  const float* qkv_w  = (const float*)d_in[1];
  const float* qkv_b  = (const float*)d_in[2];
  const float* proj_w = (const float*)d_in[3];
  const float* proj_b = (const float*)d_in[4];
  float* out = (float*)d_out;

  // dynamic smem caps (host-side attributes; idempotent)
  cudaFuncSetAttribute(hgemm_comp<HID, CfgQKV3>,
                       cudaFuncAttributeMaxDynamicSharedMemorySize, GSMEM);
  cudaFuncSetAttribute(hgemm_comp<HID, CfgProj3>,
                       cudaFuncAttributeMaxDynamicSharedMemorySize, GSMEM);
  cudaFuncSetAttribute(qk_comp_kernel,
                       cudaFuncAttributeMaxDynamicSharedMemorySize, QK_SMEM);
  cudaFuncSetAttribute(pv_hmma_kernel,
                       cudaFuncAttributeMaxDynamicSharedMemorySize, PV_SMEM);

  // 0) operand splits
  {
    __half *hidh, *hidl, *wqh, *wql, *wph, *wpl;
    cudaGetSymbolAddress((void**)&hidh, g_hidh);
    cudaGetSymbolAddress((void**)&hidl, g_hidl);
    cudaGetSymbolAddress((void**)&wqh, g_wqh);
    cudaGetSymbolAddress((void**)&wql, g_wql);
    cudaGetSymbolAddress((void**)&wph, g_wph);
    cudaGetSymbolAddress((void**)&wpl, g_wpl);
    int n1 = BATCH * SEQ * HID / 4;
    int n2 = 3 * HID * HID / 4;
    int n3 = HID * HID / 4;
    split_kernel<<<(n1 + 255) / 256, 256>>>(hidden, hidh, hidl, n1);
    split_kernel<<<(n2 + 255) / 256, 256>>>(qkv_w, wqh, wql, n2);
    split_kernel<<<(n3 + 255) / 256, 256>>>(proj_w, wph, wpl, n3);
  }

  // 1) QKV comp-HMMA (cp.async double-buffered)
  hgemm_comp<HID><<<dim3((3 * HID) / 128, (BATCH * SEQ) / 128), 256, GSMEM>>>(
      CfgQKV3{qkv_b});

  // 2) QK^T comp-HMMA per head (R11 cp.async pipelined, .cs score stores)
  qk_comp_kernel<<<dim3(SEQ / 128, SEQ / 128, HEADS), 256, QK_SMEM>>>();

  // 3) exact select + softmax (R6 algorithm, 2 rows/block)
  select_softmax_kernel<<<dim3(HEADS * SEQ / 2), 512>>>();

  // 4) PV HMMA (cp.async 2-stage ring)
  pv_hmma_kernel<<<dim3(SEQ / 128, HEADS), 256, PV_SMEM>>>();

  // 5) proj comp-HMMA (cp.async double-buffered)
  hgemm_comp<HID><<<dim3(HID / 128, (BATCH * SEQ) / 128), 256, GSMEM>>>(
      CfgProj3{proj_b, out});
}

// round 17
// speedup vs baseline: 1.0118x; 1.0036x over previous
#include <cuda_runtime.h>
#include <cuda_fp16.h>
#include <cstdint>

// VisionDynamicSparseAttention pipeline (round 17 = R16 with 4-rows-per-block select):
//  0) split kernels: hidden/qkv_w/proj_w -> fp16 hi+lo pairs
//  1) QKV via compensated fp16 HMMA, cp.async double-buffered (+bias)
//  2) Q@K^T comp-HMMA (R11 pipeline); .cs score stores
//  3) select: exact fp32 k-th largest (R6 algorithm per row, 4 rows/block
//     sharing barriers) + masked softmax -> g_p fp16
//  4) PV fp16 HMMA, cp.async 2-stage ring -> ctx fp16 hi+lo
//  5) proj via compensated fp16 HMMA, cp.async (+bias) -> d_out fp32

namespace {
constexpr int NH    = 12;
constexpr int HDIM  = 64;
constexpr int BATCH = 2;
constexpr int SEQ   = 2048;
constexpr int HID   = 768;
constexpr int HEADS = BATCH * NH;   // 24
constexpr int KSEL  = 1024;
constexpr float L2E = 1.4426950408889634f;
// hgemm tiling
constexpr int GLDA = 40;                  // halves pitch (80B rows)
constexpr int GTS  = 128 * GLDA;          // halves per tensor tile
constexpr int GSMEM = 2 * 4 * GTS * 2;    // bytes: 2 stages x 4 tensors
// qk tiling (R11)
constexpr int QLDQ = 72;                  // halves pitch (144B rows)
constexpr int QTS  = 128 * QLDQ;          // halves per tile
constexpr int QK_SMEM = 4 * QTS * 2;      // bytes: Qh,Kh,Ql,Kl resident (73728)
// pv tiling (R14)
constexpr int PLDP = 72;                  // halves pitch
constexpr int PTS  = 128 * PLDP;          // P tile halves
constexpr int VTS  = 64 * PLDP;           // V tile halves
constexpr int PSTG = PTS + VTS;           // halves per stage
constexpr int PV_SMEM = 2 * PSTG * 2;     // bytes (55296)
// select grouping
constexpr int SROWS = 4;                  // rows per select block
}

// fp16 hi/lo operand copies
__device__ __half g_hidh[BATCH * SEQ * HID];
__device__ __half g_hidl[BATCH * SEQ * HID];
__device__ __half g_wqh[3 * HID * HID];
__device__ __half g_wql[3 * HID * HID];
__device__ __half g_wph[HID * HID];
__device__ __half g_wpl[HID * HID];
// per-head q/k (hi+lo), v
__device__ __half g_qh[HEADS * SEQ * HDIM];
__device__ __half g_ql[HEADS * SEQ * HDIM];
__device__ __half g_kh[HEADS * SEQ * HDIM];
__device__ __half g_kl[HEADS * SEQ * HDIM];
__device__ __half g_vh[HEADS * SEQ * HDIM];
// attention
__device__ float  g_attn[(long long)HEADS * SEQ * SEQ];  // fp32 scores
__device__ __half g_p[(long long)HEADS * SEQ * SEQ];     // fp16 probs
// context (hi+lo for proj A operand)
__device__ __half g_ctxh[BATCH * SEQ * HID];
__device__ __half g_ctxl[BATCH * SEQ * HID];

// FMA-only exp2 (range-reduced deg-5; rel err ~2.4e-6)
__device__ __forceinline__ float fast_exp2(float y) {
  float t = y + 12582912.0f;
  int   i = __float_as_int(t);
  float f = y - (t - 12582912.0f);
  float p = 1.3333558146e-3f;
  p = fmaf(p, f, 9.6181291918e-3f);
  p = fmaf(p, f, 5.5504108665e-2f);
  p = fmaf(p, f, 2.4022650696e-1f);
  p = fmaf(p, f, 6.9314718056e-1f);
  p = fmaf(p, f, 1.0f);
  return __int_as_float(__float_as_int(p) + (i << 23));
}

// ---------------------------------------------------------------------------
// split: fp32 -> fp16 hi + lo residual
// ---------------------------------------------------------------------------
__global__ void __launch_bounds__(256) split_kernel(const float* __restrict__ src,
                                                    __half* __restrict__ hi,
                                                    __half* __restrict__ lo, int n4) {
  int i = blockIdx.x * blockDim.x + threadIdx.x;
  if (i >= n4) return;
  float4 v = ((const float4*)src)[i];
  __half hx = __float2half_rn(v.x), hy = __float2half_rn(v.y);
  __half hz = __float2half_rn(v.z), hw = __float2half_rn(v.w);
  union { __half2 h2[2]; uint2 u; } H, L;
  H.h2[0] = __halves2half2(hx, hy);
  H.h2[1] = __halves2half2(hz, hw);
  L.h2[0] = __floats2half2_rn(v.x - __half2float(hx), v.y - __half2float(hy));
  L.h2[1] = __floats2half2_rn(v.z - __half2float(hz), v.w - __half2float(hw));
  ((uint2*)hi)[i] = H.u;
  ((uint2*)lo)[i] = L.u;
}

// ---------------------------------------------------------------------------
// HMMA / async primitives
// ---------------------------------------------------------------------------
__device__ __forceinline__ void ldsm_x4(uint32_t& r0, uint32_t& r1, uint32_t& r2,
                                        uint32_t& r3, uint32_t saddr) {
  asm volatile("ldmatrix.sync.aligned.m8n8.x4.shared.b16 {%0,%1,%2,%3}, [%4];"
               : "=r"(r0), "=r"(r1), "=r"(r2), "=r"(r3) : "r"(saddr));
}
__device__ __forceinline__ void ldsm_x4_t(uint32_t& r0, uint32_t& r1, uint32_t& r2,
                                          uint32_t& r3, uint32_t saddr) {
  asm volatile("ldmatrix.sync.aligned.m8n8.x4.trans.shared.b16 {%0,%1,%2,%3}, [%4];"
               : "=r"(r0), "=r"(r1), "=r"(r2), "=r"(r3) : "r"(saddr));
}
__device__ __forceinline__ void mma16816(float* c, const uint32_t a[4],
                                         uint32_t b0, uint32_t b1) {
  asm volatile(
      "mma.sync.aligned.m16n8k16.row.col.f32.f16.f16.f32 "
      "{%0,%1,%2,%3}, {%4,%5,%6,%7}, {%8,%9}, {%0,%1,%2,%3};"
      : "+f"(c[0]), "+f"(c[1]), "+f"(c[2]), "+f"(c[3])
      : "r"(a[0]), "r"(a[1]), "r"(a[2]), "r"(a[3]), "r"(b0), "r"(b1));
}
__device__ __forceinline__ void cp_async16(uint32_t saddr, const void* g) {
  asm volatile("cp.async.cg.shared.global [%0], [%1], 16;" :: "r"(saddr), "l"(g));
}

// ---------------------------------------------------------------------------
// Compensated fp16 GEMM, cp.async 2-stage (R8/R10-proven).
// ---------------------------------------------------------------------------
template <int KDIM, class Cfg>
__global__ void __launch_bounds__(256) hgemm_comp(Cfg cfg) {
  constexpr int BK = 32;
  constexpr int NIT = KDIM / BK;
  extern __shared__ __half dynsm[];

  const __half* __restrict__ src[4] = {cfg.Ah(), cfg.Al(), cfg.Bh(), cfg.Bl()};

  const int tid = threadIdx.x;
  const int warp = tid >> 5, lane = tid & 31;
  const int warp_m = warp >> 1, warp_n = warp & 1;
  const int m0 = blockIdx.y * 128;
  const int n0 = blockIdx.x * 128;
  const int row0[4] = {m0, m0, n0, n0};

  const int lr = tid >> 2;
  const int lc = (tid & 3) << 3;

  const uint32_t sm_base = (uint32_t)__cvta_generic_to_shared(dynsm);

  float c[2][8][4];
#pragma unroll
  for (int mi = 0; mi < 2; mi++)
#pragma unroll
    for (int ni = 0; ni < 8; ni++)
#pragma unroll
      for (int j = 0; j < 4; j++) c[mi][ni][j] = 0.f;

  auto issue = [&](int stage, int k0) {
#pragma unroll
    for (int t = 0; t < 4; t++) {
      const uint32_t tbase = sm_base + (uint32_t)(stage * 4 + t) * GTS * 2;
#pragma unroll
      for (int h = 0; h < 2; h++) {
        const int r = lr + 64 * h;
        cp_async16(tbase + (uint32_t)(r * GLDA + lc) * 2,
                   &src[t][(long)(row0[t] + r) * KDIM + k0 + lc]);
      }
    }
  };

  issue(0, 0);
  asm volatile("cp.async.commit_group;" ::: "memory");

  const uint32_t a_off = ((warp_m * 32 + (lane & 15)) * GLDA + ((lane >> 4) << 3)) * 2;
  const uint32_t b_off = ((warp_n * 64 + (lane & 15)) * GLDA + ((lane >> 4) << 3)) * 2;

#pragma unroll 1
  for (int it = 0; it < NIT; it++) {
    if (it + 1 < NIT) {
      issue((it + 1) & 1, (it + 1) * BK);
      asm volatile("cp.async.commit_group;" ::: "memory");
      asm volatile("cp.async.wait_group 1;" ::: "memory");
    } else {
      asm volatile("cp.async.wait_group 0;" ::: "memory");
    }
    __syncthreads();

    const int st = it & 1;
    const uint32_t ah_b = sm_base + (uint32_t)(st * 4 + 0) * GTS * 2;
    const uint32_t al_b = sm_base + (uint32_t)(st * 4 + 1) * GTS * 2;
    const uint32_t bh_b = sm_base + (uint32_t)(st * 4 + 2) * GTS * 2;
    const uint32_t bl_b = sm_base + (uint32_t)(st * 4 + 3) * GTS * 2;

#pragma unroll
    for (int ks = 0; ks < 2; ks++) {
      uint32_t ah[2][4], al[2][4];
#pragma unroll
      for (int mi = 0; mi < 2; mi++) {
        ldsm_x4(ah[mi][0], ah[mi][1], ah[mi][2], ah[mi][3],
                ah_b + a_off + (mi * 16 * GLDA + ks * 16) * 2);
        ldsm_x4(al[mi][0], al[mi][1], al[mi][2], al[mi][3],
                al_b + a_off + (mi * 16 * GLDA + ks * 16) * 2);
      }
#pragma unroll
      for (int nig = 0; nig < 4; nig++) {
        uint32_t bh0, bh1, bh2, bh3, bl0, bl1, bl2, bl3;
        ldsm_x4(bh0, bh1, bh2, bh3, bh_b + b_off + (nig * 16 * GLDA + ks * 16) * 2);
        ldsm_x4(bl0, bl1, bl2, bl3, bl_b + b_off + (nig * 16 * GLDA + ks * 16) * 2);
#pragma unroll
        for (int mi = 0; mi < 2; mi++) {
          mma16816(c[mi][2 * nig + 0], ah[mi], bh0, bh2);
          mma16816(c[mi][2 * nig + 1], ah[mi], bh1, bh3);
          mma16816(c[mi][2 * nig + 0], ah[mi], bl0, bl2);
          mma16816(c[mi][2 * nig + 1], ah[mi], bl1, bl3);
          mma16816(c[mi][2 * nig + 0], al[mi], bh0, bh2);
          mma16816(c[mi][2 * nig + 1], al[mi], bh1, bh3);
        }
      }
    }
    __syncthreads();
  }
  cfg.epi(c, m0, n0, warp_m, warp_n, lane);
}

// ---------------- Stage 1: QKV (comp-HMMA) ----------------
struct CfgQKV3 {
  const float* bias;
  __device__ __forceinline__ const __half* Ah() const { return g_hidh; }
  __device__ __forceinline__ const __half* Al() const { return g_hidl; }
  __device__ __forceinline__ const __half* Bh() const { return g_wqh; }
  __device__ __forceinline__ const __half* Bl() const { return g_wql; }
  __device__ __forceinline__ void handle(int m, int n, float v0, float v1) const {
    const int b = m >> 11, s = m & (SEQ - 1);
    const int sec = n / HID;
    const int rem = n - sec * HID;
    const int h = rem >> 6, d = rem & 63;
    const long base = ((long)((b * NH + h) * SEQ + s)) * HDIM + d;
    v0 += bias[n];
    v1 += bias[n + 1];
    if (sec == 0) { v0 *= 0.125f; v1 *= 0.125f; }
    __half h0 = __float2half_rn(v0), h1 = __float2half_rn(v1);
    __half2 hi = __halves2half2(h0, h1);
    if (sec == 2) {
      *(__half2*)&g_vh[base] = hi;
      return;
    }
    __half2 lo = __floats2half2_rn(v0 - __half2float(h0), v1 - __half2float(h1));
    if (sec == 0) {
      *(__half2*)&g_qh[base] = hi;
      *(__half2*)&g_ql[base] = lo;
    } else {
      *(__half2*)&g_kh[base] = hi;
      *(__half2*)&g_kl[base] = lo;
    }
  }
  __device__ __forceinline__ void epi(const float c[2][8][4], int m0, int n0,
                                      int warp_m, int warp_n, int lane) const {
#pragma unroll
    for (int mi = 0; mi < 2; mi++) {
      const int r = m0 + warp_m * 32 + mi * 16 + (lane >> 2);
#pragma unroll
      for (int ni = 0; ni < 8; ni++) {
        const int n = n0 + warp_n * 64 + ni * 8 + 2 * (lane & 3);
        handle(r, n, c[mi][ni][0], c[mi][ni][1]);
        handle(r + 8, n, c[mi][ni][2], c[mi][ni][3]);
      }
    }
  }
};

// ---------------- Stage 5: proj (comp-HMMA) ----------------
struct CfgProj3 {
  const float* bias;
  float* out;
  __device__ __forceinline__ const __half* Ah() const { return g_ctxh; }
  __device__ __forceinline__ const __half* Al() const { return g_ctxl; }
  __device__ __forceinline__ const __half* Bh() const { return g_wph; }
  __device__ __forceinline__ const __half* Bl() const { return g_wpl; }
  __device__ __forceinline__ void epi(const float c[2][8][4], int m0, int n0,
                                      int warp_m, int warp_n, int lane) const {
#pragma unroll
    for (int mi = 0; mi < 2; mi++) {
      const int r = m0 + warp_m * 32 + mi * 16 + (lane >> 2);
#pragma unroll
      for (int ni = 0; ni < 8; ni++) {
        const int n = n0 + warp_n * 64 + ni * 8 + 2 * (lane & 3);
        const float b0 = bias[n], b1 = bias[n + 1];
        *(float2*)&out[(long)r * HID + n] =
            make_float2(c[mi][ni][0] + b0, c[mi][ni][1] + b1);
        *(float2*)&out[(long)(r + 8) * HID + n] =
            make_float2(c[mi][ni][2] + b0, c[mi][ni][3] + b1);
      }
    }
  }
};

// ---------------------------------------------------------------------------
// Stage 2: compensated QK^T, cp.async pipelined (R11); .cs score stores.
// ---------------------------------------------------------------------------
__global__ void __launch_bounds__(256) qk_comp_kernel() {
  extern __shared__ __half qsm[];

  const int head = blockIdx.z;
  const int m0 = blockIdx.y * 128;
  const int n0 = blockIdx.x * 128;
  const long qoff = (long)head * SEQ * HDIM;

  const int tid = threadIdx.x;
  const int warp = tid >> 5, lane = tid & 31;
  const int warp_m = warp >> 1, warp_n = warp & 1;

  // tile order: 0=Qh, 1=Kh (group A); 2=Ql, 3=Kl (group B)
  const __half* __restrict__ src[4] = {g_qh + qoff, g_kh + qoff,
                                       g_ql + qoff, g_kl + qoff};
  const int row0[4] = {m0, n0, m0, n0};

  const int lrow = tid >> 1;
  const int lcol = (tid & 1) * 32;
  const uint32_t smb = (uint32_t)__cvta_generic_to_shared(qsm);

#pragma unroll
  for (int t = 0; t < 2; t++) {
    const uint32_t tbase = smb + (uint32_t)t * QTS * 2;
    const __half* g = &src[t][(long)(row0[t] + lrow) * HDIM + lcol];
#pragma unroll
    for (int i = 0; i < 4; i++)
      cp_async16(tbase + (uint32_t)(lrow * QLDQ + lcol + i * 8) * 2, g + i * 8);
  }
  asm volatile("cp.async.commit_group;" ::: "memory");
#pragma unroll
  for (int t = 2; t < 4; t++) {
    const uint32_t tbase = smb + (uint32_t)t * QTS * 2;
    const __half* g = &src[t][(long)(row0[t] + lrow) * HDIM + lcol];
#pragma unroll
    for (int i = 0; i < 4; i++)
      cp_async16(tbase + (uint32_t)(lrow * QLDQ + lcol + i * 8) * 2, g + i * 8);
  }
  asm volatile("cp.async.commit_group;" ::: "memory");

  float c[2][8][4];
#pragma unroll
  for (int mi = 0; mi < 2; mi++)
#pragma unroll
    for (int ni = 0; ni < 8; ni++)
#pragma unroll
      for (int j = 0; j < 4; j++) c[mi][ni][j] = 0.f;

  const uint32_t a_off = ((warp_m * 32 + (lane & 15)) * QLDQ + ((lane >> 4) << 3)) * 2;
  const uint32_t b_off = ((warp_n * 64 + (lane & 15)) * QLDQ + ((lane >> 4) << 3)) * 2;

  const int pa[3] = {0, 0, 2};
  const int pb[3] = {1, 3, 1};

  asm volatile("cp.async.wait_group 1;" ::: "memory");
  __syncthreads();

#pragma unroll 1
  for (int ph = 0; ph < 3; ph++) {
    if (ph == 1) {
      asm volatile("cp.async.wait_group 0;" ::: "memory");
      __syncthreads();
    }
    const uint32_t ab = smb + (uint32_t)pa[ph] * QTS * 2;
    const uint32_t bb = smb + (uint32_t)pb[ph] * QTS * 2;
#pragma unroll
    for (int ks = 0; ks < 4; ks++) {
      uint32_t a[2][4];
#pragma unroll
      for (int mi = 0; mi < 2; mi++)
        ldsm_x4(a[mi][0], a[mi][1], a[mi][2], a[mi][3],
                ab + a_off + (mi * 16 * QLDQ + ks * 16) * 2);
#pragma unroll
      for (int nig = 0; nig < 4; nig++) {
        uint32_t b0, b1, b2, b3;
        ldsm_x4(b0, b1, b2, b3, bb + b_off + (nig * 16 * QLDQ + ks * 16) * 2);
#pragma unroll
        for (int mi = 0; mi < 2; mi++) {
          mma16816(c[mi][2 * nig + 0], a[mi], b0, b2);
          mma16816(c[mi][2 * nig + 1], a[mi], b1, b3);
        }
      }
    }
  }

  float* C = g_attn + (long long)head * SEQ * SEQ;
#pragma unroll
  for (int mi = 0; mi < 2; mi++) {
    const int r = m0 + warp_m * 32 + mi * 16 + (lane >> 2);
#pragma unroll
    for (int ni = 0; ni < 8; ni++) {
      const int col = n0 + warp_n * 64 + ni * 8 + 2 * (lane & 3);
      __stcs((float2*)&C[(long)r * SEQ + col],
             make_float2(c[mi][ni][0], c[mi][ni][1]));
      __stcs((float2*)&C[(long)(r + 8) * SEQ + col],
             make_float2(c[mi][ni][2], c[mi][ni][3]));
    }
  }
}

// ---------------------------------------------------------------------------
// Stage 3: exact fp32 k-th largest + masked softmax -> fp16 P.
// R6 algorithm per row, FOUR rows per 1024-thread block sharing barriers.
// g = row group (tid>>8), t = index within group (0..255).
// ---------------------------------------------------------------------------
__global__ void __launch_bounds__(1024) select_softmax_kernel() {
  const int tid = threadIdx.x;
  const int g = tid >> 8;         // which row this thread serves (0..3)
  const int t = tid & 255;        // index within the row group
  const int warp = t >> 5, lane = tid & 31;
  const long long row = (long long)blockIdx.x * SROWS + g;
  const float* srow = g_attn + row * SEQ;
  __half* rowp = g_p + row * SEQ;

  __shared__ int hist[SROWS][256];
  __shared__ int scan[SROWS][256];
  __shared__ float redf[SROWS][8];
  __shared__ float s_max[SROWS], s_inv[SROWS];
  __shared__ int s_bucket[SROWS], s_r[SROWS], s_cnt[SROWS];
  __shared__ unsigned s_thr[SROWS];
  __shared__ unsigned cand[SROWS][2048];

  float4 va = __ldcs((const float4*)&srow[t * 8]);
  float4 vb = __ldcs((const float4*)&srow[t * 8 + 4]);
  float myv[8] = {va.x, va.y, va.z, va.w, vb.x, vb.y, vb.z, vb.w};

  // row max (warps are wholly within one row group)
  float mx = myv[0];
#pragma unroll
  for (int i = 1; i < 8; i++) mx = fmaxf(mx, myv[i]);
#pragma unroll
  for (int o = 16; o > 0; o >>= 1) mx = fmaxf(mx, __shfl_xor_sync(~0u, mx, o));
  if (lane == 0) redf[g][warp] = mx;
  hist[g][t] = 0;
  __syncthreads();
  if (warp == 0) {  // warp 0 of each row group
    float m2 = (lane < 8) ? redf[g][lane] : -3.4e38f;
#pragma unroll
    for (int o = 4; o > 0; o >>= 1) m2 = fmaxf(m2, __shfl_xor_sync(~0u, m2, o));
    if (lane == 0) s_max[g] = m2;
  }

  unsigned key[8];
#pragma unroll
  for (int i = 0; i < 8; i++) {
    int b = __float_as_int(myv[i]);
    key[i] = (unsigned)b ^ ((b < 0) ? 0xFFFFFFFFu : 0x80000000u);
  }

#pragma unroll
  for (int i = 0; i < 8; i++) atomicAdd(&hist[g][key[i] >> 24], 1);
  __syncthreads();

  scan[g][t] = hist[g][t];
  __syncthreads();
#pragma unroll
  for (int off = 1; off < 256; off <<= 1) {
    int v = scan[g][t] + ((t + off < 256) ? scan[g][t + off] : 0);
    __syncthreads();
    scan[g][t] = v;
    __syncthreads();
  }
  if (scan[g][t] >= KSEL && (t == 255 || scan[g][t + 1] < KSEL)) {
    s_bucket[g] = t;
    s_r[g] = KSEL - ((t == 255) ? 0 : scan[g][t + 1]);
    s_cnt[g] = 0;
  }
  __syncthreads();
  const unsigned bucket = (unsigned)s_bucket[g];

#pragma unroll
  for (int i = 0; i < 8; i++)
    if ((key[i] >> 24) == bucket) cand[g][atomicAdd(&s_cnt[g], 1)] = key[i];
  __syncthreads();

  if (warp == 0) {  // one warp per row group does its bitselect, all in parallel
    const int c = s_cnt[g];
    int r = s_r[g];
    unsigned P = bucket << 24;
#pragma unroll 1
    for (int b = 23; b >= 0; b--) {
      const unsigned want = (P | (1u << b)) >> b;
      int cnt = 0;
      for (int i = lane; i < c; i += 32)
        if ((cand[g][i] >> b) == want) cnt++;
#pragma unroll
      for (int o = 16; o > 0; o >>= 1) cnt += __shfl_xor_sync(~0u, cnt, o);
      if (r <= cnt) P |= 1u << b;
      else r -= cnt;
    }
    if (lane == 0) s_thr[g] = P;
  }
  __syncthreads();
  const unsigned thr = s_thr[g];
  const float rowmax = s_max[g];

  const float nm = -rowmax * L2E;
  float myp[8];
  float esum = 0.f;
#pragma unroll
  for (int i = 0; i < 8; i++) {
    float e = (key[i] >= thr) ? fast_exp2(fmaf(myv[i], L2E, nm)) : 0.f;
    myp[i] = e;
    esum += e;
  }
#pragma unroll
  for (int o = 16; o > 0; o >>= 1) esum += __shfl_xor_sync(~0u, esum, o);
  if (lane == 0) redf[g][warp] = esum;
  __syncthreads();
  if (warp == 0) {
    float z = (lane < 8) ? redf[g][lane] : 0.f;
#pragma unroll
    for (int o = 4; o > 0; o >>= 1) z += __shfl_xor_sync(~0u, z, o);
    if (lane == 0) s_inv[g] = 1.f / z;
  }
  __syncthreads();
  const float inv = s_inv[g];

  union { __half2 h[4]; uint4 u; } pk;
#pragma unroll
  for (int i = 0; i < 4; i++)
    pk.h[i] = __floats2half2_rn(myp[2 * i] * inv, myp[2 * i + 1] * inv);
  __stcs((uint4*)&rowp[t * 8], pk.u);
}

// ---------------------------------------------------------------------------
// Stage 4: P@V per head, fp16 HMMA, cp.async 2-stage ring (R14-proven).
// ---------------------------------------------------------------------------
__global__ void __launch_bounds__(256) pv_hmma_kernel() {
  constexpr int NIT = SEQ / 64;  // 32
  extern __shared__ __half pvsm[];

  const int head = blockIdx.y;
  const int m0 = blockIdx.x * 128;
  const __half* __restrict__ P = g_p + (long long)head * SEQ * SEQ;
  const __half* __restrict__ V = g_vh + (long)head * SEQ * HDIM;

  const int tid = threadIdx.x;
  const int warp = tid >> 5, lane = tid & 31;
  const int wm0 = warp * 16;

  float c[8][4];
#pragma unroll
  for (int i = 0; i < 8; i++)
#pragma unroll
    for (int j = 0; j < 4; j++) c[i][j] = 0.f;

  const int pr = tid >> 3, pc = (tid & 7) << 3;
  const uint32_t smb = (uint32_t)__cvta_generic_to_shared(pvsm);

  auto issue = [&](int stage, int k0) {
    const uint32_t pb = smb + (uint32_t)stage * PSTG * 2;
    const uint32_t vb = pb + (uint32_t)PTS * 2;
#pragma unroll
    for (int l = 0; l < 4; l++)
      cp_async16(pb + (uint32_t)((pr + 32 * l) * PLDP + pc) * 2,
                 &P[(long)(m0 + pr + 32 * l) * SEQ + k0 + pc]);
#pragma unroll
    for (int l = 0; l < 2; l++)
      cp_async16(vb + (uint32_t)((pr + 32 * l) * PLDP + pc) * 2,
                 &V[(long)(k0 + pr + 32 * l) * HDIM + pc]);
  };

  issue(0, 0);
  asm volatile("cp.async.commit_group;" ::: "memory");

  const uint32_t a_off = ((wm0 + (lane & 15)) * PLDP + ((lane >> 4) << 3)) * 2;
  const uint32_t b_row = (lane & 7) + (lane & 8);
  const uint32_t b_off = (b_row * PLDP + ((lane & 16) >> 1)) * 2;

#pragma unroll 1
  for (int it = 0; it < NIT; it++) {
    if (it + 1 < NIT) {
      issue((it + 1) & 1, (it + 1) * 64);
      asm volatile("cp.async.commit_group;" ::: "memory");
      asm volatile("cp.async.wait_group 1;" ::: "memory");
    } else {
      asm volatile("cp.async.wait_group 0;" ::: "memory");
    }
    __syncthreads();

    const uint32_t so = (uint32_t)(it & 1) * PSTG * 2;
    const uint32_t a_base = smb + so + a_off;
    const uint32_t b_base = smb + so + (uint32_t)PTS * 2 + b_off;

#pragma unroll
    for (int ks = 0; ks < 4; ks++) {
      uint32_t a[4];
      ldsm_x4(a[0], a[1], a[2], a[3], a_base + ks * 16 * 2);
#pragma unroll
      for (int g = 0; g < 4; g++) {
        uint32_t b0, b1, b2, b3;
        ldsm_x4_t(b0, b1, b2, b3, b_base + (ks * 16 * PLDP + g * 16) * 2);
        mma16816(c[2 * g + 0], a, b0, b1);
        mma16816(c[2 * g + 1], a, b2, b3);
      }
    }
    __syncthreads();
  }

  // epilogue -> ctx fp16 hi+lo [B,S,H]
  const int b = head / NH, h = head - b * NH;
  const int r0 = lane >> 2, col0 = (lane & 3) * 2;
  const long rowbase0 = (long)(b * SEQ + m0 + wm0 + r0) * HID + h * HDIM;
  const long rowbase1 = rowbase0 + 8L * HID;
#pragma unroll
  for (int nt = 0; nt < 8; nt++) {
    const int n = nt * 8 + col0;
    {
      float v0 = c[nt][0], v1 = c[nt][1];
      __half h0 = __float2half_rn(v0), h1 = __float2half_rn(v1);
      *(__half2*)&g_ctxh[rowbase0 + n] = __halves2half2(h0, h1);
      *(__half2*)&g_ctxl[rowbase0 + n] =
          __floats2half2_rn(v0 - __half2float(h0), v1 - __half2float(h1));
    }
    {
      float v0 = c[nt][2], v1 = c[nt][3];
      __half h0 = __float2half_rn(v0), h1 = __float2half_rn(v1);
      *(__half2*)&g_ctxh[rowbase1 + n] = __halves2half2(h0, h1);
      *(__half2*)&g_ctxl[rowbase1 + n] =
          __floats2half2_rn(v0 - __half2float(h0), v1 - __half2float(h1));
    }
  }
}

// ---------------------------------------------------------------------------
extern "C" void kernel_launch(void* const* d_in, const int* in_sizes, int n_in,
                              void* d_out, int out_size) {
  const float* hidden = (const float*)d_in[0];
  const float* qkv_w  = (const float*)d_in[1];
  const float* qkv_b  = (const float*)d_in[2];
  const float* proj_w = (const float*)d_in[3];
  const float* proj_b = (const float*)d_in[4];
  float* out = (float*)d_out;

  // dynamic smem caps (host-side attributes; idempotent)
  cudaFuncSetAttribute(hgemm_comp<HID, CfgQKV3>,
                       cudaFuncAttributeMaxDynamicSharedMemorySize, GSMEM);
  cudaFuncSetAttribute(hgemm_comp<HID, CfgProj3>,
                       cudaFuncAttributeMaxDynamicSharedMemorySize, GSMEM);
  cudaFuncSetAttribute(qk_comp_kernel,
                       cudaFuncAttributeMaxDynamicSharedMemorySize, QK_SMEM);
  cudaFuncSetAttribute(pv_hmma_kernel,
                       cudaFuncAttributeMaxDynamicSharedMemorySize, PV_SMEM);

  // 0) operand splits
  {
    __half *hidh, *hidl, *wqh, *wql, *wph, *wpl;
    cudaGetSymbolAddress((void**)&hidh, g_hidh);
    cudaGetSymbolAddress((void**)&hidl, g_hidl);
    cudaGetSymbolAddress((void**)&wqh, g_wqh);
    cudaGetSymbolAddress((void**)&wql, g_wql);
    cudaGetSymbolAddress((void**)&wph, g_wph);
    cudaGetSymbolAddress((void**)&wpl, g_wpl);
    int n1 = BATCH * SEQ * HID / 4;
    int n2 = 3 * HID * HID / 4;
    int n3 = HID * HID / 4;
    split_kernel<<<(n1 + 255) / 256, 256>>>(hidden, hidh, hidl, n1);
    split_kernel<<<(n2 + 255) / 256, 256>>>(qkv_w, wqh, wql, n2);
    split_kernel<<<(n3 + 255) / 256, 256>>>(proj_w, wph, wpl, n3);
  }

  // 1) QKV comp-HMMA (cp.async double-buffered)
  hgemm_comp<HID><<<dim3((3 * HID) / 128, (BATCH * SEQ) / 128), 256, GSMEM>>>(
      CfgQKV3{qkv_b});

  // 2) QK^T comp-HMMA per head (R11 cp.async pipelined, .cs score stores)
  qk_comp_kernel<<<dim3(SEQ / 128, SEQ / 128, HEADS), 256, QK_SMEM>>>();

  // 3) exact select + softmax (R6 algorithm, 4 rows/block)
  select_softmax_kernel<<<dim3(HEADS * SEQ / SROWS), 1024>>>();

  // 4) PV HMMA (cp.async 2-stage ring)
  pv_hmma_kernel<<<dim3(SEQ / 128, HEADS), 256, PV_SMEM>>>();

  // 5) proj comp-HMMA (cp.async double-buffered)
  hgemm_comp<HID><<<dim3(HID / 128, (BATCH * SEQ) / 128), 256, GSMEM>>>(
      CfgProj3{proj_b, out});
}